// round 2
// baseline (speedup 1.0000x reference)
#include <cuda_runtime.h>
#include <cuda_bf16.h>
#include <cstddef>

// Problem constants
#define RNN_B 32
#define RNN_T 512
#define RNN_E 1024
#define RNN_H 1024
#define RNN_M (RNN_B * RNN_T)   // 16384 rows for the input projection

// Device scratch (allocation-free rule: __device__ globals)
__device__ float g_xp[RNN_M * RNN_H];      // 64 MB: x @ W_ih^T + b_ih + b_hh
__device__ float g_WT[RNN_H * RNN_H];      // 4 MB: W_hh transposed -> [k][j]

// ---------------------------------------------------------------------------
// Kernel 1: transpose W_hh [H][H] -> g_WT [k][j] so step-kernel weight reads
// are coalesced across j.
// ---------------------------------------------------------------------------
__global__ void transpose_whh(const float* __restrict__ W) {
    __shared__ float tile[32][33];
    int x = blockIdx.x * 32 + threadIdx.x;   // col of W
    int y = blockIdx.y * 32 + threadIdx.y;   // row of W
    tile[threadIdx.y][threadIdx.x] = W[y * RNN_H + x];
    __syncthreads();
    int xo = blockIdx.y * 32 + threadIdx.x;  // col of WT (= row of W)
    int yo = blockIdx.x * 32 + threadIdx.y;  // row of WT (= col of W)
    g_WT[yo * RNN_H + xo] = tile[threadIdx.x][threadIdx.y];
}

// ---------------------------------------------------------------------------
// Kernel 2: xp = x @ W_ih^T + (b_ih + b_hh)
// Tiled SGEMM: C[M=16384][N=1024], A=x [M][K], B=W_ih [N][K] (both K-major).
// BM=BN=64, BK=16, 256 threads, 4x4 register tile per thread.
// ---------------------------------------------------------------------------
#define BM 64
#define BN 64
#define BK 16

__global__ __launch_bounds__(256) void xp_gemm(
    const float* __restrict__ x,
    const float* __restrict__ Wih,
    const float* __restrict__ bih,
    const float* __restrict__ bhh)
{
    __shared__ float As[BK][BM];
    __shared__ float Bs[BK][BN];

    const int bm = blockIdx.y * BM;      // row tile in M
    const int bn = blockIdx.x * BN;      // col tile in H
    const int tid = threadIdx.x;

    const int tm = (tid / 16) * 4;       // 0..60
    const int tn = (tid % 16) * 4;       // 0..60

    // Each thread loads one float4 of A and one of B per BK slab
    const int lr = tid / 4;              // 0..63 : row within tile
    const int lk = (tid % 4) * 4;        // 0,4,8,12 : k offset

    const float* Aptr = x   + (size_t)(bm + lr) * RNN_E;
    const float* Bptr = Wih + (size_t)(bn + lr) * RNN_E;

    float acc[4][4] = {};

    for (int k0 = 0; k0 < RNN_E; k0 += BK) {
        float4 av = *(const float4*)(Aptr + k0 + lk);
        float4 bv = *(const float4*)(Bptr + k0 + lk);
        As[lk + 0][lr] = av.x; As[lk + 1][lr] = av.y;
        As[lk + 2][lr] = av.z; As[lk + 3][lr] = av.w;
        Bs[lk + 0][lr] = bv.x; Bs[lk + 1][lr] = bv.y;
        Bs[lk + 2][lr] = bv.z; Bs[lk + 3][lr] = bv.w;
        __syncthreads();

        #pragma unroll
        for (int k = 0; k < BK; k++) {
            float4 a4 = *(const float4*)&As[k][tm];
            float4 b4 = *(const float4*)&Bs[k][tn];
            float a[4] = {a4.x, a4.y, a4.z, a4.w};
            float b[4] = {b4.x, b4.y, b4.z, b4.w};
            #pragma unroll
            for (int i = 0; i < 4; i++)
                #pragma unroll
                for (int j = 0; j < 4; j++)
                    acc[i][j] += a[i] * b[j];
        }
        __syncthreads();
    }

    float bias[4];
    #pragma unroll
    for (int j = 0; j < 4; j++)
        bias[j] = bih[bn + tn + j] + bhh[bn + tn + j];

    #pragma unroll
    for (int i = 0; i < 4; i++) {
        float4 v = make_float4(acc[i][0] + bias[0], acc[i][1] + bias[1],
                               acc[i][2] + bias[2], acc[i][3] + bias[3]);
        *(float4*)&g_xp[(size_t)(bm + tm + i) * RNN_H + bn + tn] = v;
    }
}

// ---------------------------------------------------------------------------
// Kernel 3: one recurrence step.
//   out[b][t][j] = tanh(xp[b][t][j] + sum_k out[b][t-1][k] * W_hh[j][k])
// Grid: (32 j-tiles of 32, 4 b-tiles of 8) = 128 blocks, 256 threads.
// Each thread owns one (b, j) output; h_{t-1} rows staged in smem.
// Weight reads coalesced via g_WT[k][j].
// ---------------------------------------------------------------------------
#define JT 32
#define BT 8

__global__ __launch_bounds__(256) void rnn_step(float* __restrict__ out, int t) {
    __shared__ float sh[BT][RNN_H];

    const int j  = blockIdx.x * JT + (threadIdx.x & 31);
    const int bb = threadIdx.x >> 5;                 // 0..7
    const int b  = blockIdx.y * BT + bb;

    float acc = 0.0f;

    if (t > 0) {
        // cooperative load of 8 h_{t-1} rows
        const size_t prev_base = (size_t)(t - 1) * RNN_H;
        for (int i = threadIdx.x; i < BT * RNN_H; i += 256) {
            int br = i >> 10;          // /1024
            int k  = i & (RNN_H - 1);
            sh[br][k] = out[(size_t)(blockIdx.y * BT + br) * (RNN_T * RNN_H)
                            + prev_base + k];
        }
        __syncthreads();

        const float* __restrict__ w = g_WT + j;      // stride RNN_H over k
        const float* __restrict__ hrow = sh[bb];
        #pragma unroll 8
        for (int k = 0; k < RNN_H; k++)
            acc += hrow[k] * w[(size_t)k * RNN_H];
    }

    const size_t idx = (size_t)b * (RNN_T * RNN_H) + (size_t)t * RNN_H + j;
    out[idx] = tanhf(g_xp[idx] + acc);
}

// ---------------------------------------------------------------------------
// Launch
// ---------------------------------------------------------------------------
extern "C" void kernel_launch(void* const* d_in, const int* in_sizes, int n_in,
                              void* d_out, int out_size) {
    const float* x    = (const float*)d_in[0];   // [32,512,1024]
    const float* W_ih = (const float*)d_in[1];   // [1024,1024]
    const float* W_hh = (const float*)d_in[2];   // [1024,1024]
    const float* b_ih = (const float*)d_in[3];   // [1024]
    const float* b_hh = (const float*)d_in[4];   // [1024]
    float* out = (float*)d_out;                  // [32,512,1024]

    (void)in_sizes; (void)n_in; (void)out_size;

    // W_hh -> W_hh^T (k-major) for coalesced step reads
    transpose_whh<<<dim3(RNN_H / 32, RNN_H / 32), dim3(32, 32)>>>(W_hh);

    // Input projection for all timesteps
    xp_gemm<<<dim3(RNN_H / BN, RNN_M / BM), 256>>>(x, W_ih, b_ih, b_hh);

    // Sequential scan: 512 dependent step kernels
    for (int t = 0; t < RNN_T; t++)
        rnn_step<<<dim3(RNN_H / JT, RNN_B / BT), 256>>>(out, t);
}

// round 3
// speedup vs baseline: 2.2796x; 2.2796x over previous
#include <cuda_runtime.h>
#include <cuda_bf16.h>
#include <cstddef>
#include <cstdint>

#define RNN_B 32
#define RNN_T 512
#define RNN_E 1024
#define RNN_H 1024
#define RNN_M (RNN_B * RNN_T)

#define NBLK 128          // persistent grid size (<= 148 SMs -> co-resident)
#define JPB 8             // output columns per block

// Device scratch
__device__ float g_xp[RNN_M * RNN_H];          // 64 MB: x @ W_ih^T + bias
__device__ float g_hT[2][RNN_H * RNN_B];       // transposed h double buffer: [k][b]
__device__ unsigned g_count;                    // grid barrier counter (monotonic per launch)
__device__ volatile unsigned g_release;         // grid barrier release step

// ---------------------------------------------------------------------------
// Reset barrier state (must run before each rnn_scan so graph replays work)
// ---------------------------------------------------------------------------
__global__ void reset_barrier() {
    g_count = 0;
    g_release = 0;
}

// ---------------------------------------------------------------------------
// xp = x @ W_ih^T + (b_ih + b_hh)   [fp32 SGEMM, 64x64x16 tiles, 4x4/thread]
// ---------------------------------------------------------------------------
#define BM 64
#define BN 64
#define BK 16

__global__ __launch_bounds__(256) void xp_gemm(
    const float* __restrict__ x,
    const float* __restrict__ Wih,
    const float* __restrict__ bih,
    const float* __restrict__ bhh)
{
    __shared__ float As[BK][BM];
    __shared__ float Bs[BK][BN];

    const int bm = blockIdx.y * BM;
    const int bn = blockIdx.x * BN;
    const int tid = threadIdx.x;

    const int tm = (tid / 16) * 4;
    const int tn = (tid % 16) * 4;

    const int lr = tid / 4;
    const int lk = (tid % 4) * 4;

    const float* Aptr = x   + (size_t)(bm + lr) * RNN_E;
    const float* Bptr = Wih + (size_t)(bn + lr) * RNN_E;

    float acc[4][4] = {};

    for (int k0 = 0; k0 < RNN_E; k0 += BK) {
        float4 av = *(const float4*)(Aptr + k0 + lk);
        float4 bv = *(const float4*)(Bptr + k0 + lk);
        As[lk + 0][lr] = av.x; As[lk + 1][lr] = av.y;
        As[lk + 2][lr] = av.z; As[lk + 3][lr] = av.w;
        Bs[lk + 0][lr] = bv.x; Bs[lk + 1][lr] = bv.y;
        Bs[lk + 2][lr] = bv.z; Bs[lk + 3][lr] = bv.w;
        __syncthreads();

        #pragma unroll
        for (int k = 0; k < BK; k++) {
            float4 a4 = *(const float4*)&As[k][tm];
            float4 b4 = *(const float4*)&Bs[k][tn];
            float a[4] = {a4.x, a4.y, a4.z, a4.w};
            float b[4] = {b4.x, b4.y, b4.z, b4.w};
            #pragma unroll
            for (int i = 0; i < 4; i++)
                #pragma unroll
                for (int j = 0; j < 4; j++)
                    acc[i][j] += a[i] * b[j];
        }
        __syncthreads();
    }

    float bias[4];
    #pragma unroll
    for (int j = 0; j < 4; j++)
        bias[j] = bih[bn + tn + j] + bhh[bn + tn + j];

    #pragma unroll
    for (int i = 0; i < 4; i++) {
        float4 v = make_float4(acc[i][0] + bias[0], acc[i][1] + bias[1],
                               acc[i][2] + bias[2], acc[i][3] + bias[3]);
        *(float4*)&g_xp[(size_t)(bm + tm + i) * RNN_H + bn + tn] = v;
    }
}

// ---------------------------------------------------------------------------
// Persistent scan kernel.
// Grid 128 blocks x 256 thr. Block owns 8 j-columns. Warp w owns k-chunk
// [w*128, w*128+128). Lane = batch b.
// W_hh held in registers for all 512 steps: lane s of warp w holds
//   wreg[c][jj] = W_hh[j0+jj][wk0 + 4*s + c]
// and per-k values are broadcast with __shfl_sync(., ., ks) (uniform src).
// h crosses steps via transposed global double buffer g_hT[t&1][k][b];
// reads use __ldcg (L1 bypass) so no cross-SM staleness.
// ---------------------------------------------------------------------------
__device__ __forceinline__ void grid_barrier(unsigned target) {
    __threadfence();
    __syncthreads();
    if (threadIdx.x == 0) {
        unsigned old = atomicAdd(&g_count, 1u);
        if (old == target * NBLK - 1u) {
            g_release = target;            // last arriver releases
        } else {
            while (g_release < target) { __nanosleep(32); }
        }
    }
    __syncthreads();
}

__global__ __launch_bounds__(256) void rnn_scan(
    const float* __restrict__ Whh,
    float* __restrict__ out)
{
    __shared__ float red[8][RNN_B * 9 + 8];   // padded: [warp][b*9 + jj]

    const int tid  = threadIdx.x;
    const int w    = tid >> 5;                // warp 0..7  -> k-chunk
    const int lane = tid & 31;                // lane = b in main loop
    const int j0   = blockIdx.x * JPB;
    const int wk0  = w * 128;

    // Preload W_hh slice into registers (distributed across lanes).
    float wreg[4][JPB];
    #pragma unroll
    for (int c = 0; c < 4; c++)
        #pragma unroll
        for (int jj = 0; jj < JPB; jj++)
            wreg[c][jj] = Whh[(size_t)(j0 + jj) * RNN_H + wk0 + 4 * lane + c];

    // Reducer-side thread mapping (also used for t = 0)
    const int rjj = tid & 7;
    const int rb  = tid >> 3;

    // ---- t = 0: h = tanh(xp) ----
    {
        const size_t m = (size_t)rb * RNN_T;            // t = 0
        float v = tanhf(g_xp[m * RNN_H + j0 + rjj]);
        out[m * RNN_H + j0 + rjj] = v;
        g_hT[0][(j0 + rjj) * RNN_B + rb] = v;
    }
    grid_barrier(1);

    // ---- t = 1 .. T-1 ----
    for (int t = 1; t < RNN_T; t++) {
        const float* hprev = g_hT[(t - 1) & 1];

        float acc[JPB] = {};
        const float* hrow = hprev + (size_t)wk0 * RNN_B + lane;

        #pragma unroll 4
        for (int ks = 0; ks < 32; ks++) {
            float hv[4];
            #pragma unroll
            for (int c = 0; c < 4; c++)
                hv[c] = __ldcg(hrow + (4 * ks + c) * RNN_B);
            #pragma unroll
            for (int c = 0; c < 4; c++)
                #pragma unroll
                for (int jj = 0; jj < JPB; jj++)
                    acc[jj] += hv[c] * __shfl_sync(0xffffffffu, wreg[c][jj], ks);
        }

        // stash partials (conflict-free: 9*lane distinct mod 32)
        #pragma unroll
        for (int jj = 0; jj < JPB; jj++)
            red[w][lane * 9 + jj] = acc[jj];
        __syncthreads();

        // reduce across the 8 k-chunks, add xp, tanh, write out + hT
        float s = g_xp[((size_t)rb * RNN_T + t) * RNN_H + j0 + rjj];
        #pragma unroll
        for (int w2 = 0; w2 < 8; w2++)
            s += red[w2][rb * 9 + rjj];
        float hn = tanhf(s);
        out[((size_t)rb * RNN_T + t) * RNN_H + j0 + rjj] = hn;
        g_hT[t & 1][(j0 + rjj) * RNN_B + rb] = hn;

        if (t < RNN_T - 1) grid_barrier((unsigned)t + 1);
    }
}

// ---------------------------------------------------------------------------
// Launch
// ---------------------------------------------------------------------------
extern "C" void kernel_launch(void* const* d_in, const int* in_sizes, int n_in,
                              void* d_out, int out_size) {
    const float* x    = (const float*)d_in[0];
    const float* W_ih = (const float*)d_in[1];
    const float* W_hh = (const float*)d_in[2];
    const float* b_ih = (const float*)d_in[3];
    const float* b_hh = (const float*)d_in[4];
    float* out = (float*)d_out;

    (void)in_sizes; (void)n_in; (void)out_size;

    reset_barrier<<<1, 1>>>();

    xp_gemm<<<dim3(RNN_H / BN, RNN_M / BM), 256>>>(x, W_ih, b_ih, b_hh);

    rnn_scan<<<NBLK, 256>>>(W_hh, out);
}

// round 4
// speedup vs baseline: 4.6779x; 2.0521x over previous
#include <cuda_runtime.h>
#include <cuda_bf16.h>
#include <cstddef>
#include <cstdint>

typedef unsigned long long ull;

#define RNN_B 32
#define RNN_T 512
#define RNN_E 1024
#define RNN_H 1024
#define RNN_M (RNN_B * RNN_T)

#define NBLK 128            // persistent grid (<=148 SMs -> co-resident)
#define JPB 8               // output columns per block
#define SCAN_THREADS 512
#define NW 16               // warps per scan block
#define K2_PER_WARP (RNN_H / 2 / NW)   // 32 k-pairs per warp

// Device scratch
__device__ float g_xp[RNN_M * RNN_H];      // 64 MB: x @ W_ih^T + bias
__device__ float g_h2[2][RNN_H * RNN_B];   // pair-interleaved h: float idx = k2*64 + 2b + (k&1)
__device__ unsigned g_count;
__device__ volatile unsigned g_release;

// ---------------- f32x2 packed helpers (FFMA2 only reachable via PTX) -------
__device__ __forceinline__ ull pack2(float x, float y) {
    ull r; asm("mov.b64 %0,{%1,%2};" : "=l"(r) : "f"(x), "f"(y)); return r;
}
__device__ __forceinline__ void ffma2(ull& d, ull a, ull b) {
    asm("fma.rn.f32x2 %0,%1,%2,%0;" : "+l"(d) : "l"(a), "l"(b));
}
__device__ __forceinline__ float2 unpack2(ull v) {
    float lo, hi; asm("mov.b64 {%0,%1},%2;" : "=f"(lo), "=f"(hi) : "l"(v));
    return make_float2(lo, hi);
}

// ---------------------------------------------------------------------------
__global__ void reset_barrier() { g_count = 0; g_release = 0; }

// ---------------------------------------------------------------------------
// xp = x @ W_ih^T + (b_ih + b_hh). 64x64x16 tiles, 4x4/thread, FFMA2 inner.
// ---------------------------------------------------------------------------
#define BM 64
#define BN 64
#define BK 16

__global__ __launch_bounds__(256) void xp_gemm(
    const float* __restrict__ x,
    const float* __restrict__ Wih,
    const float* __restrict__ bih,
    const float* __restrict__ bhh)
{
    __shared__ float As[BK][BM];
    __shared__ float Bs[BK][BN];

    const int bm = blockIdx.y * BM;
    const int bn = blockIdx.x * BN;
    const int tid = threadIdx.x;

    const int tm = (tid / 16) * 4;
    const int tn = (tid % 16) * 4;

    const int lr = tid / 4;
    const int lk = (tid % 4) * 4;

    const float* Aptr = x   + (size_t)(bm + lr) * RNN_E;
    const float* Bptr = Wih + (size_t)(bn + lr) * RNN_E;

    ull accp[4][2] = {};   // pairs over j: (j0,j1),(j2,j3) per row i

    for (int k0 = 0; k0 < RNN_E; k0 += BK) {
        float4 av = *(const float4*)(Aptr + k0 + lk);
        float4 bv = *(const float4*)(Bptr + k0 + lk);
        As[lk + 0][lr] = av.x; As[lk + 1][lr] = av.y;
        As[lk + 2][lr] = av.z; As[lk + 3][lr] = av.w;
        Bs[lk + 0][lr] = bv.x; Bs[lk + 1][lr] = bv.y;
        Bs[lk + 2][lr] = bv.z; Bs[lk + 3][lr] = bv.w;
        __syncthreads();

        #pragma unroll
        for (int k = 0; k < BK; k++) {
            float4 a4 = *(const float4*)&As[k][tm];
            float4 b4 = *(const float4*)&Bs[k][tn];
            ull bp0 = pack2(b4.x, b4.y);
            ull bp1 = pack2(b4.z, b4.w);
            float a[4] = {a4.x, a4.y, a4.z, a4.w};
            #pragma unroll
            for (int i = 0; i < 4; i++) {
                ull ad = pack2(a[i], a[i]);
                ffma2(accp[i][0], ad, bp0);
                ffma2(accp[i][1], ad, bp1);
            }
        }
        __syncthreads();
    }

    float bias[4];
    #pragma unroll
    for (int j = 0; j < 4; j++)
        bias[j] = bih[bn + tn + j] + bhh[bn + tn + j];

    #pragma unroll
    for (int i = 0; i < 4; i++) {
        float2 f0 = unpack2(accp[i][0]);
        float2 f1 = unpack2(accp[i][1]);
        float4 v = make_float4(f0.x + bias[0], f0.y + bias[1],
                               f1.x + bias[2], f1.y + bias[3]);
        *(float4*)&g_xp[(size_t)(bm + tm + i) * RNN_H + bn + tn] = v;
    }
}

// ---------------------------------------------------------------------------
// Grid barrier (atomic arrival + release flag), reset each launch.
// ---------------------------------------------------------------------------
__device__ __forceinline__ void grid_barrier(unsigned target) {
    __threadfence();
    __syncthreads();
    if (threadIdx.x == 0) {
        unsigned old = atomicAdd(&g_count, 1u);
        if (old == target * NBLK - 1u) {
            g_release = target;
        } else {
            while (g_release < target) { __nanosleep(32); }
        }
    }
    __syncthreads();
}

// ---------------------------------------------------------------------------
// Persistent scan. 128 blocks x 512 thr. Block owns 8 j-columns; warp w owns
// k-pairs [w*32, w*32+32); lane = batch b.
// Weights live in smem as k-pairs: sw[k2][jj] = (W[j][2k2], W[j][2k2+1]),
// read via uniform (broadcast) LDS.128 — no shuffles.
// h crosses steps via pair-interleaved global double buffer (one LDG.64
// feeds two k's of FFMA2); horizontal add of the two halves at the end.
// ---------------------------------------------------------------------------
__global__ __launch_bounds__(SCAN_THREADS) void rnn_scan(
    const float* __restrict__ Whh,
    float* __restrict__ out)
{
    __shared__ ull   sw[RNN_H / 2][JPB];       // 32 KB weights
    __shared__ float red[NW][RNN_B * 9];       // 18 KB partials (pad 9 vs 8)

    const int tid  = threadIdx.x;
    const int w    = tid >> 5;
    const int lane = tid & 31;
    const int j0   = blockIdx.x * JPB;

    // Load weight slice as packed k-pairs (coalesced: k2 fastest).
    for (int idx = tid; idx < (RNN_H / 2) * JPB; idx += SCAN_THREADS) {
        int jj = idx >> 9;                 // 0..7
        int k2 = idx & (RNN_H / 2 - 1);    // 0..511
        sw[k2][jj] = *(const ull*)&Whh[(size_t)(j0 + jj) * RNN_H + 2 * k2];
    }
    __syncthreads();

    const int rjj = tid & 7;
    const int rb  = tid >> 3;              // valid when tid < 256

    // ---- t = 0 ----
    if (tid < 256) {
        const size_t m = (size_t)rb * RNN_T;
        float v = tanhf(__ldcs(&g_xp[m * RNN_H + j0 + rjj]));
        out[m * RNN_H + j0 + rjj] = v;
        int j = j0 + rjj;
        __stcg(&g_h2[0][(j >> 1) * 64 + rb * 2 + (j & 1)], v);
    }
    grid_barrier(1);

    const int k2lo = w * K2_PER_WARP;

    for (int t = 1; t < RNN_T; t++) {
        // prefetch xp early (independent of barrier / h)
        float xpv = 0.0f;
        if (tid < 256)
            xpv = __ldcs(&g_xp[((size_t)rb * RNN_T + t) * RNN_H + j0 + rjj]);

        const ull* __restrict__ hp = (const ull*)g_h2[(t - 1) & 1];

        ull acc[JPB] = {};
        #pragma unroll 4
        for (int k2 = k2lo; k2 < k2lo + K2_PER_WARP; k2++) {
            ull hv = __ldcg(&hp[k2 * 32 + lane]);        // (h[2k2], h[2k2+1]) for b=lane
            const ull* wr = sw[k2];
            ulonglong2 q0 = *(const ulonglong2*)&wr[0];
            ulonglong2 q1 = *(const ulonglong2*)&wr[2];
            ulonglong2 q2 = *(const ulonglong2*)&wr[4];
            ulonglong2 q3 = *(const ulonglong2*)&wr[6];
            ffma2(acc[0], hv, q0.x); ffma2(acc[1], hv, q0.y);
            ffma2(acc[2], hv, q1.x); ffma2(acc[3], hv, q1.y);
            ffma2(acc[4], hv, q2.x); ffma2(acc[5], hv, q2.y);
            ffma2(acc[6], hv, q3.x); ffma2(acc[7], hv, q3.y);
        }

        #pragma unroll
        for (int jj = 0; jj < JPB; jj++) {
            float2 f = unpack2(acc[jj]);
            red[w][lane * 9 + jj] = f.x + f.y;          // conflict-free (9 coprime 32)
        }
        __syncthreads();

        if (tid < 256) {
            float s = xpv;
            #pragma unroll
            for (int w2 = 0; w2 < NW; w2++)
                s += red[w2][rb * 9 + rjj];
            float hn = tanhf(s);
            out[((size_t)rb * RNN_T + t) * RNN_H + j0 + rjj] = hn;
            int j = j0 + rjj;
            __stcg(&g_h2[t & 1][(j >> 1) * 64 + rb * 2 + (j & 1)], hn);
        }

        if (t < RNN_T - 1) grid_barrier((unsigned)t + 1);
    }
}

// ---------------------------------------------------------------------------
extern "C" void kernel_launch(void* const* d_in, const int* in_sizes, int n_in,
                              void* d_out, int out_size) {
    const float* x    = (const float*)d_in[0];
    const float* W_ih = (const float*)d_in[1];
    const float* W_hh = (const float*)d_in[2];
    const float* b_ih = (const float*)d_in[3];
    const float* b_hh = (const float*)d_in[4];
    float* out = (float*)d_out;

    (void)in_sizes; (void)n_in; (void)out_size;

    reset_barrier<<<1, 1>>>();
    xp_gemm<<<dim3(RNN_H / BN, RNN_M / BM), 256>>>(x, W_ih, b_ih, b_hh);
    rnn_scan<<<NBLK, SCAN_THREADS>>>(W_hh, out);
}